// round 3
// baseline (speedup 1.0000x reference)
#include <cuda_runtime.h>
#include <cuda_bf16.h>
#include <cstdint>

// ---------------------------------------------------------------------------
// GAT layer: B=4, N=4096, F_in=F_out=128
//   Wh = h @ W;  si = Wh@a_i; sj = Wh@a_j
//   e_ij = leakyrelu(si_i + sj_j) masked by adj; softmax over j
//   out = elu( softmax(e) @ Wh )
// Kernel 1: Wh (fp32) -> V (tf32), si, sj
// Kernel 2: fused masked-softmax + PV matmul via mma.sync tf32
// ---------------------------------------------------------------------------

#define NB   4
#define NN   4096
#define NF   128
#define BM   64
#define BN   64

__device__ float g_V[(size_t)NB * NN * NF];   // Wh, tf32-rounded, 8 MB
__device__ float g_si[NB * NN];
__device__ float g_sj[NB * NN];

__device__ __forceinline__ float to_tf32(float x) {
    float y;
    asm("cvt.rna.tf32.f32 %0, %1;" : "=f"(y) : "f"(x));
    return y;
}

// ---------------------------------------------------------------------------
// Kernel 1: 8 rows per block, 128 threads. Each thread owns one output col.
// ---------------------------------------------------------------------------
__global__ __launch_bounds__(128) void gat_k1(const float* __restrict__ h,
                                              const float* __restrict__ W,
                                              const float* __restrict__ a) {
    __shared__ float hs[8][128];
    __shared__ float red[2][8][4];
    const int tid = threadIdx.x;
    const int base = blockIdx.x * 8;   // global row in [0, NB*NN)

#pragma unroll
    for (int r = 0; r < 8; r++)
        hs[r][tid] = h[(size_t)(base + r) * NF + tid];
    __syncthreads();

    float acc[8];
#pragma unroll
    for (int r = 0; r < 8; r++) acc[r] = 0.f;

#pragma unroll 4
    for (int f = 0; f < NF; f++) {
        const float w = W[f * NF + tid];
#pragma unroll
        for (int r = 0; r < 8; r++)
            acc[r] = fmaf(hs[r][f], w, acc[r]);
    }

    const float ai = a[tid];
    const float aj = a[NF + tid];
    const int lane = tid & 31, warp = tid >> 5;

#pragma unroll
    for (int r = 0; r < 8; r++) {
        g_V[(size_t)(base + r) * NF + tid] = to_tf32(acc[r]);
        float pi = acc[r] * ai;
        float pj = acc[r] * aj;
#pragma unroll
        for (int off = 16; off > 0; off >>= 1) {
            pi += __shfl_xor_sync(0xffffffffu, pi, off);
            pj += __shfl_xor_sync(0xffffffffu, pj, off);
        }
        if (lane == 0) { red[0][r][warp] = pi; red[1][r][warp] = pj; }
    }
    __syncthreads();
    if (tid < 16) {
        const int r = tid & 7, which = tid >> 3;
        const float s = red[which][r][0] + red[which][r][1] +
                        red[which][r][2] + red[which][r][3];
        (which ? g_sj : g_si)[base + r] = s;
    }
}

// ---------------------------------------------------------------------------
// Kernel 2: fused masked softmax + PV (mma.sync m16n8k8 tf32)
// Grid: NB * (NN/BM) = 256 blocks, 256 threads (8 warps).
// Warp (w&3) -> 16-row m-stripe; (w>>2) -> 64-col n-half.
// smem: Ps[64][68] tf32, Vs[64][136] tf32, sis[64], rsum[64].
// Ps stride 68 and Vs stride 136 chosen so mma fragment LDS are conflict-free.
// ---------------------------------------------------------------------------
#define PS_STRIDE 68
#define VS_STRIDE 136
#define SMEM_FLOATS (BM * PS_STRIDE + BN * VS_STRIDE + 64 + 64)

__global__ __launch_bounds__(256) void gat_k2(const int* __restrict__ adj,
                                              float* __restrict__ out) {
    extern __shared__ float smem[];
    float* Ps   = smem;
    float* Vs   = smem + BM * PS_STRIDE;
    float* sis  = Vs + BN * VS_STRIDE;
    float* rsum = sis + 64;

    const int tid  = threadIdx.x;
    const int lane = tid & 31, warp = tid >> 5;
    const int b  = blockIdx.x >> 6;
    const int i0 = (blockIdx.x & 63) * BM;

    if (tid < 64) sis[tid] = g_si[b * NN + i0 + tid];

    // P-phase mapping: 16 row-groups x 16 col-groups of 4
    const int prb = tid >> 4;            // 0..15
    const int cg  = (tid & 15) * 4;      // 0,4,...,60

    const int*   adj_b = adj + ((size_t)(b * NN + i0)) * NN;
    const float* sjb   = g_sj + b * NN;
    const float* Vg    = g_V + (size_t)b * NN * NF;

    const int mw = (warp & 3) * 16;      // warp m-stripe base row
    const int nw = (warp >> 2) * 64;     // warp n-half base col
    const int ar = lane >> 2;            // groupID
    const int ac = lane & 3;             // threadID-in-group

    float acc[8][4];
#pragma unroll
    for (int i = 0; i < 8; i++)
#pragma unroll
        for (int j = 0; j < 4; j++) acc[i][j] = 0.f;
    float rs[4] = {0.f, 0.f, 0.f, 0.f};

    const uint32_t* Psu = (const uint32_t*)Ps;
    const uint32_t* Vsu = (const uint32_t*)Vs;

    for (int jt = 0; jt < NN / BN; jt++) {
        const int j0 = jt * BN;
        __syncthreads();   // previous mma done reading Ps/Vs (also covers sis init)

        // ---- Phase 1: scores -> P tile (tf32), plus row-sum partials ----
        const float4 sj4 = *(const float4*)(sjb + j0 + cg);
#pragma unroll
        for (int ii = 0; ii < 4; ii++) {
            const int row = ii * 16 + prb;
            const float siv = sis[row];
            const int4 ad = *(const int4*)(adj_b + (size_t)row * NN + j0 + cg);
            float e0 = siv + sj4.x; e0 = e0 > 0.f ? e0 : 0.2f * e0;
            float e1 = siv + sj4.y; e1 = e1 > 0.f ? e1 : 0.2f * e1;
            float e2 = siv + sj4.z; e2 = e2 > 0.f ? e2 : 0.2f * e2;
            float e3 = siv + sj4.w; e3 = e3 > 0.f ? e3 : 0.2f * e3;
            const float p0 = ad.x ? __expf(e0) : 0.f;
            const float p1 = ad.y ? __expf(e1) : 0.f;
            const float p2 = ad.z ? __expf(e2) : 0.f;
            const float p3 = ad.w ? __expf(e3) : 0.f;
            rs[ii] += (p0 + p1) + (p2 + p3);
            float4 q;
            q.x = to_tf32(p0); q.y = to_tf32(p1);
            q.z = to_tf32(p2); q.w = to_tf32(p3);
            *(float4*)(Ps + row * PS_STRIDE + cg) = q;
        }

        // ---- Phase 1b: stage V tile (64 x 128 tf32) ----
#pragma unroll
        for (int q = 0; q < 8; q++) {
            const int l  = tid + q * 256;
            const int vr = l >> 5;
            const int c4 = (l & 31) << 2;
            const float4 v = *(const float4*)(Vg + (size_t)(j0 + vr) * NF + c4);
            *(float4*)(Vs + vr * VS_STRIDE + c4) = v;
        }
        __syncthreads();

        // ---- Phase 2: acc += P(64x64) @ V(64x128) via m16n8k8 tf32 ----
#pragma unroll
        for (int k8 = 0; k8 < 8; k8++) {
            const int k0 = k8 * 8;
            const uint32_t a0 = Psu[(mw + ar)     * PS_STRIDE + k0 + ac];
            const uint32_t a1 = Psu[(mw + ar + 8) * PS_STRIDE + k0 + ac];
            const uint32_t a2 = Psu[(mw + ar)     * PS_STRIDE + k0 + ac + 4];
            const uint32_t a3 = Psu[(mw + ar + 8) * PS_STRIDE + k0 + ac + 4];
#pragma unroll
            for (int nt = 0; nt < 8; nt++) {
                const int n0 = nw + nt * 8;
                const uint32_t b0 = Vsu[(k0 + ac)     * VS_STRIDE + n0 + ar];
                const uint32_t b1 = Vsu[(k0 + ac + 4) * VS_STRIDE + n0 + ar];
                asm volatile(
                    "mma.sync.aligned.m16n8k8.row.col.f32.tf32.tf32.f32 "
                    "{%0,%1,%2,%3}, {%4,%5,%6,%7}, {%8,%9}, {%0,%1,%2,%3};\n"
                    : "+f"(acc[nt][0]), "+f"(acc[nt][1]),
                      "+f"(acc[nt][2]), "+f"(acc[nt][3])
                    : "r"(a0), "r"(a1), "r"(a2), "r"(a3), "r"(b0), "r"(b1));
            }
        }
    }
    __syncthreads();

    // ---- Row-sum reduction (reuse Ps area) ----
#pragma unroll
    for (int ii = 0; ii < 4; ii++)
        Ps[(ii * 16 + prb) * 16 + (tid & 15)] = rs[ii];
    __syncthreads();
    if (tid < 64) {
        float s = 0.f;
#pragma unroll
        for (int k = 0; k < 16; k++) s += Ps[tid * 16 + k];
        rsum[tid] = s;
    }
    __syncthreads();

    // ---- Epilogue: normalize, ELU, store ----
    const float r0 = rsum[mw + ar];
    const float r1 = rsum[mw + ar + 8];
    const float inv0 = r0 > 0.f ? 1.f / r0 : 0.f;
    const float inv1 = r1 > 0.f ? 1.f / r1 : 0.f;
    const size_t obase = ((size_t)(b * NN + i0)) * NF;

#pragma unroll
    for (int nt = 0; nt < 8; nt++) {
        const int col = nw + nt * 8 + ac * 2;
        float x0 = acc[nt][0] * inv0, x1 = acc[nt][1] * inv0;
        float y0 = acc[nt][2] * inv1, y1 = acc[nt][3] * inv1;
        x0 = x0 > 0.f ? x0 : expm1f(x0);
        x1 = x1 > 0.f ? x1 : expm1f(x1);
        y0 = y0 > 0.f ? y0 : expm1f(y0);
        y1 = y1 > 0.f ? y1 : expm1f(y1);
        *(float2*)(out + obase + (size_t)(mw + ar) * NF + col)     = make_float2(x0, x1);
        *(float2*)(out + obase + (size_t)(mw + ar + 8) * NF + col) = make_float2(y0, y1);
    }
}

// ---------------------------------------------------------------------------
extern "C" void kernel_launch(void* const* d_in, const int* in_sizes, int n_in,
                              void* d_out, int out_size) {
    const float* h   = (const float*)d_in[0];   // (4,4096,128) f32
    const int*   adj = (const int*)d_in[1];     // (4,4096,4096) i32
    const float* W   = (const float*)d_in[2];   // (128,128) f32
    const float* a   = (const float*)d_in[3];   // (256,) f32
    float* out = (float*)d_out;                 // (4,4096,128) f32

    static_assert(SMEM_FLOATS * 4 < 228 * 1024, "smem");
    cudaFuncSetAttribute(gat_k2, cudaFuncAttributeMaxDynamicSharedMemorySize,
                         SMEM_FLOATS * 4);

    gat_k1<<<(NB * NN) / 8, 128>>>(h, W, a);
    gat_k2<<<NB * (NN / BM), 256, SMEM_FLOATS * 4>>>(adj, out);
}

// round 5
// speedup vs baseline: 1.5856x; 1.5856x over previous
#include <cuda_runtime.h>
#include <cuda_bf16.h>
#include <cstdint>

// ---------------------------------------------------------------------------
// GAT layer: B=4, N=4096, F_in=F_out=128
// K1: Wh (fp32) -> V (tf32), si, sj
// K2: fused masked-softmax + PV via mma.sync tf32, software-pipelined:
//     - adj/sj register prefetch (next tile) hidden under MMA phase
//     - cp.async double-buffered V smem staging
//     - warp tile m32 x n32 (B-fragment reuse across 2 m-tiles)
// ---------------------------------------------------------------------------

#define NB   4
#define NN   4096
#define NF   128
#define BM   64
#define BN   64

__device__ float g_V[(size_t)NB * NN * NF];
__device__ float g_si[NB * NN];
__device__ float g_sj[NB * NN];

__device__ __forceinline__ float to_tf32(float x) {
    float y;
    asm("cvt.rna.tf32.f32 %0, %1;" : "=f"(y) : "f"(x));
    return y;
}

// ---------------------------------------------------------------------------
// Kernel 1: Wh = h @ W, si, sj
// ---------------------------------------------------------------------------
__global__ __launch_bounds__(128) void gat_k1(const float* __restrict__ h,
                                              const float* __restrict__ W,
                                              const float* __restrict__ a) {
    __shared__ float hs[8][128];
    __shared__ float red[2][8][4];
    const int tid = threadIdx.x;
    const int base = blockIdx.x * 8;

#pragma unroll
    for (int r = 0; r < 8; r++)
        hs[r][tid] = h[(size_t)(base + r) * NF + tid];
    __syncthreads();

    float acc[8];
#pragma unroll
    for (int r = 0; r < 8; r++) acc[r] = 0.f;

#pragma unroll 4
    for (int f = 0; f < NF; f++) {
        const float w = W[f * NF + tid];
#pragma unroll
        for (int r = 0; r < 8; r++)
            acc[r] = fmaf(hs[r][f], w, acc[r]);
    }

    const float ai = a[tid];
    const float aj = a[NF + tid];
    const int lane = tid & 31, warp = tid >> 5;

#pragma unroll
    for (int r = 0; r < 8; r++) {
        g_V[(size_t)(base + r) * NF + tid] = to_tf32(acc[r]);
        float pi = acc[r] * ai;
        float pj = acc[r] * aj;
#pragma unroll
        for (int off = 16; off > 0; off >>= 1) {
            pi += __shfl_xor_sync(0xffffffffu, pi, off);
            pj += __shfl_xor_sync(0xffffffffu, pj, off);
        }
        if (lane == 0) { red[0][r][warp] = pi; red[1][r][warp] = pj; }
    }
    __syncthreads();
    if (tid < 16) {
        const int r = tid & 7, which = tid >> 3;
        const float s = red[which][r][0] + red[which][r][1] +
                        red[which][r][2] + red[which][r][3];
        (which ? g_sj : g_si)[base + r] = s;
    }
}

// ---------------------------------------------------------------------------
// Kernel 2
// ---------------------------------------------------------------------------
#define PS_STRIDE 68
#define VS_STRIDE 136
#define SMEM_FLOATS (BM * PS_STRIDE + 2 * BN * VS_STRIDE + 64 + 64)

#define CP_ASYNC16(dst_u32, src_ptr) \
    asm volatile("cp.async.cg.shared.global [%0], [%1], 16;" \
                 :: "r"(dst_u32), "l"(src_ptr))
#define CP_COMMIT()  asm volatile("cp.async.commit_group;" ::: "memory")
#define CP_WAIT1()   asm volatile("cp.async.wait_group 1;"  ::: "memory")

__global__ __launch_bounds__(256, 2) void gat_k2(const int* __restrict__ adj,
                                                 float* __restrict__ out) {
    extern __shared__ float smem[];
    float* Ps   = smem;                                // 64 x 68
    float* Vs   = smem + BM * PS_STRIDE;               // 2 x 64 x 136
    float* sis  = Vs + 2 * BN * VS_STRIDE;
    float* rsum = sis + 64;

    const int tid  = threadIdx.x;
    const int lane = tid & 31, warp = tid >> 5;
    const int b  = blockIdx.x >> 6;
    const int i0 = (blockIdx.x & 63) * BM;

    if (tid < 64) sis[tid] = g_si[b * NN + i0 + tid];

    // P-phase mapping: thread handles rows {ii*16+prb}, cols cg..cg+3
    const int prb = tid >> 4;
    const int cg  = (tid & 15) * 4;

    const int*   adj_b = adj + ((size_t)(b * NN + i0)) * NN;
    const float* sjb   = g_sj + b * NN;
    const float* Vg    = g_V + (size_t)b * NN * NF;

    // MMA warp tiling: m32 x n32
    const int wm = (warp & 1) * 32;
    const int wn = (warp >> 1) * 32;
    const int ar = lane >> 2;            // groupID (rows / B-cols)
    const int ac = lane & 3;             // thread-in-group (k)

    // V staging: thread copies 8 x 16B
    const int vr0 = tid >> 5;            // +8 per q
    const int vc4 = (tid & 31) << 2;

    const uint32_t vs_smem_base =
        (uint32_t)__cvta_generic_to_shared(Vs);

    float acc[2][4][4];
#pragma unroll
    for (int mt = 0; mt < 2; mt++)
#pragma unroll
        for (int nt = 0; nt < 4; nt++)
#pragma unroll
            for (int j = 0; j < 4; j++) acc[mt][nt][j] = 0.f;
    float rs[4] = {0.f, 0.f, 0.f, 0.f};

    const uint32_t* Psu = (const uint32_t*)Ps;

    // ---- prologue: stage V tile 0 (buf 0), prefetch adj/sj tile 0 ----
    int4 pad[4];
    float4 psj;
#pragma unroll
    for (int q = 0; q < 8; q++) {
        const int vr = vr0 + q * 8;
        CP_ASYNC16(vs_smem_base + (uint32_t)((vr * VS_STRIDE + vc4) * 4),
                   Vg + (size_t)vr * NF + vc4);
    }
    CP_COMMIT();
#pragma unroll
    for (int ii = 0; ii < 4; ii++)
        pad[ii] = *(const int4*)(adj_b + (size_t)(ii * 16 + prb) * NN + cg);
    psj = *(const float4*)(sjb + cg);
    __syncthreads();   // sis visible

    for (int jt = 0; jt < NN / BN; jt++) {
        const int buf = jt & 1;

        // ---- P tile from prefetched regs ----
#pragma unroll
        for (int ii = 0; ii < 4; ii++) {
            const int row = ii * 16 + prb;
            const float siv = sis[row];
            const int4 ad = pad[ii];
            float e0 = siv + psj.x; e0 = e0 > 0.f ? e0 : 0.2f * e0;
            float e1 = siv + psj.y; e1 = e1 > 0.f ? e1 : 0.2f * e1;
            float e2 = siv + psj.z; e2 = e2 > 0.f ? e2 : 0.2f * e2;
            float e3 = siv + psj.w; e3 = e3 > 0.f ? e3 : 0.2f * e3;
            const float p0 = ad.x ? __expf(e0) : 0.f;
            const float p1 = ad.y ? __expf(e1) : 0.f;
            const float p2 = ad.z ? __expf(e2) : 0.f;
            const float p3 = ad.w ? __expf(e3) : 0.f;
            rs[ii] += (p0 + p1) + (p2 + p3);
            float4 q;
            q.x = to_tf32(p0); q.y = to_tf32(p1);
            q.z = to_tf32(p2); q.w = to_tf32(p3);
            *(float4*)(Ps + row * PS_STRIDE + cg) = q;
        }

        // ---- prefetch tile jt+1: V via cp.async, adj/sj into regs ----
        if (jt + 1 < NN / BN) {
            const int j1 = (jt + 1) * BN;
            const uint32_t vb = vs_smem_base +
                                (uint32_t)((buf ^ 1) * BN * VS_STRIDE * 4);
#pragma unroll
            for (int q = 0; q < 8; q++) {
                const int vr = vr0 + q * 8;
                CP_ASYNC16(vb + (uint32_t)((vr * VS_STRIDE + vc4) * 4),
                           Vg + (size_t)(j1 + vr) * NF + vc4);
            }
            CP_COMMIT();
#pragma unroll
            for (int ii = 0; ii < 4; ii++)
                pad[ii] = *(const int4*)(adj_b + (size_t)(ii * 16 + prb) * NN +
                                         j1 + cg);
            psj = *(const float4*)(sjb + j1 + cg);
        } else {
            CP_COMMIT();   // keep group count uniform
        }
        CP_WAIT1();        // V(jt) complete (V(jt+1) still in flight)
        __syncthreads();   // Ps + Vs[buf] ready for all threads

        // ---- MMA: acc += P(64x64) @ V(64x128) ----
        const uint32_t* Vsu = (const uint32_t*)(Vs + buf * BN * VS_STRIDE);
#pragma unroll
        for (int k8 = 0; k8 < 8; k8++) {
            const int k0 = k8 * 8;
            uint32_t afr[2][4];
#pragma unroll
            for (int mt = 0; mt < 2; mt++) {
                const int row = wm + mt * 16 + ar;
                afr[mt][0] = Psu[row * PS_STRIDE + k0 + ac];
                afr[mt][1] = Psu[(row + 8) * PS_STRIDE + k0 + ac];
                afr[mt][2] = Psu[row * PS_STRIDE + k0 + ac + 4];
                afr[mt][3] = Psu[(row + 8) * PS_STRIDE + k0 + ac + 4];
            }
#pragma unroll
            for (int nt = 0; nt < 4; nt++) {
                const int n0 = wn + nt * 8;
                const uint32_t b0 = Vsu[(k0 + ac)     * VS_STRIDE + n0 + ar];
                const uint32_t b1 = Vsu[(k0 + ac + 4) * VS_STRIDE + n0 + ar];
#pragma unroll
                for (int mt = 0; mt < 2; mt++) {
                    asm volatile(
                        "mma.sync.aligned.m16n8k8.row.col.f32.tf32.tf32.f32 "
                        "{%0,%1,%2,%3}, {%4,%5,%6,%7}, {%8,%9}, {%0,%1,%2,%3};\n"
                        : "+f"(acc[mt][nt][0]), "+f"(acc[mt][nt][1]),
                          "+f"(acc[mt][nt][2]), "+f"(acc[mt][nt][3])
                        : "r"(afr[mt][0]), "r"(afr[mt][1]),
                          "r"(afr[mt][2]), "r"(afr[mt][3]),
                          "r"(b0), "r"(b1));
                }
            }
        }
        __syncthreads();   // MMA done before next P-phase overwrites Ps
    }

    // ---- Row-sum reduction (reuse Ps area) ----
#pragma unroll
    for (int ii = 0; ii < 4; ii++)
        Ps[(ii * 16 + prb) * 16 + (tid & 15)] = rs[ii];
    __syncthreads();
    if (tid < 64) {
        float s = 0.f;
#pragma unroll
        for (int k = 0; k < 16; k++) s += Ps[tid * 16 + k];
        rsum[tid] = s;
    }
    __syncthreads();

    // ---- Epilogue: normalize, ELU, store ----
    const size_t obase = ((size_t)(b * NN + i0)) * NF;
#pragma unroll
    for (int mt = 0; mt < 2; mt++) {
        const int r0i = wm + mt * 16 + ar;
        const float rr0 = rsum[r0i];
        const float rr1 = rsum[r0i + 8];
        const float inv0 = rr0 > 0.f ? 1.f / rr0 : 0.f;
        const float inv1 = rr1 > 0.f ? 1.f / rr1 : 0.f;
#pragma unroll
        for (int nt = 0; nt < 4; nt++) {
            const int col = wn + nt * 8 + ac * 2;
            float x0 = acc[mt][nt][0] * inv0, x1 = acc[mt][nt][1] * inv0;
            float y0 = acc[mt][nt][2] * inv1, y1 = acc[mt][nt][3] * inv1;
            x0 = x0 > 0.f ? x0 : expm1f(x0);
            x1 = x1 > 0.f ? x1 : expm1f(x1);
            y0 = y0 > 0.f ? y0 : expm1f(y0);
            y1 = y1 > 0.f ? y1 : expm1f(y1);
            *(float2*)(out + obase + (size_t)r0i * NF + col)       = make_float2(x0, x1);
            *(float2*)(out + obase + (size_t)(r0i + 8) * NF + col) = make_float2(y0, y1);
        }
    }
}

// ---------------------------------------------------------------------------
extern "C" void kernel_launch(void* const* d_in, const int* in_sizes, int n_in,
                              void* d_out, int out_size) {
    const float* h   = (const float*)d_in[0];
    const int*   adj = (const int*)d_in[1];
    const float* W   = (const float*)d_in[2];
    const float* a   = (const float*)d_in[3];
    float* out = (float*)d_out;

    static_assert(SMEM_FLOATS * 4 < 114 * 1024, "smem too big for 2 CTAs/SM");
    cudaFuncSetAttribute(gat_k2, cudaFuncAttributeMaxDynamicSharedMemorySize,
                         SMEM_FLOATS * 4);

    gat_k1<<<(NB * NN) / 8, 128>>>(h, W, a);
    gat_k2<<<NB * (NN / BM), 256, SMEM_FLOATS * 4>>>(adj, out);
}